// round 16
// baseline (speedup 1.0000x reference)
#include <cuda_runtime.h>
#include <cuda_bf16.h>
#include <cstdint>
#include <cstddef>

#define BB 256
#define TT 512
#define II 128
#define HH 256
#define GG 768

typedef unsigned long long u64;

// ---------------- bf16 helpers ----------------
__device__ __forceinline__ uint32_t pkbf(float x, float y) {
    __nv_bfloat162 h = __floats2bfloat162_rn(x, y);
    return *(uint32_t*)&h;
}
__device__ __forceinline__ float bfres(float x) {   // x - bf16(x)
    return x - __bfloat162float(__float2bfloat16(x));
}
__device__ __forceinline__ void ldsm_x4t(uint32_t& r0, uint32_t& r1,
                                         uint32_t& r2, uint32_t& r3, uint32_t a) {
    asm volatile("ldmatrix.sync.aligned.m8n8.x4.trans.shared.b16 {%0,%1,%2,%3}, [%4];"
                 : "=r"(r0), "=r"(r1), "=r"(r2), "=r"(r3) : "r"(a));
}
__device__ __forceinline__ void mma16816(float& c0, float& c1, float& c2, float& c3,
                                         uint32_t a0, uint32_t a1, uint32_t a2, uint32_t a3,
                                         uint32_t b0, uint32_t b1) {
    asm("mma.sync.aligned.m16n8k16.row.col.f32.bf16.bf16.f32 "
        "{%0,%1,%2,%3}, {%4,%5,%6,%7}, {%8,%9}, {%0,%1,%2,%3};"
        : "+f"(c0), "+f"(c1), "+f"(c2), "+f"(c3)
        : "r"(a0), "r"(a1), "r"(a2), "r"(a3), "r"(b0), "r"(b1));
}

// ---------------------------------------------------------------------------
// FUSED GRU: input projection + recurrence in ONE persistent kernel.
// 32 clusters x 4 CTAs, 384 threads. Per step, each warp's GEMM covers
// K = 128 (x, staged 1 step ahead) + 256 (h, k-permuted own-slice overlap).
// ldmatrix.x4.trans loads hi+lo fragments in one instruction (lanes 0-15
// address hi rows, lanes 16-31 the ^16 lo rows).
// ---------------------------------------------------------------------------
#define TPB2 384

#define OFF_W2HH 0                        // 12*16*32*16 = 98304
#define OFF_W1IH 98304                    // 12*8*32*16  = 49152
#define OFF_W2IH 147456                   // 49152
#define OFF_HSM  196608                   // 2*256*32 = 16384
#define OFF_XSM  212992                   // 2*128*32 = 8192
#define OFF_PS   221184                   // 256*8*4  = 8192
#define OFF_BSM  229376                   // 256*4 = 1024
#define OFF_MBAR 230400                   // 8
#define SM2_BYTES 230408

__device__ __forceinline__ void mbar_waitc(uint32_t mbar, uint32_t parity) {
    uint32_t done;
    asm volatile(
        "{\n\t.reg .pred p;\n\t"
        "mbarrier.try_wait.parity.acquire.cluster.shared::cta.b64 p, [%1], %2;\n\t"
        "selp.b32 %0, 1, 0, p;\n\t}"
        : "=r"(done) : "r"(mbar), "r"(parity) : "memory");
    if (!done) {
        asm volatile(
            "{\n\t.reg .pred P1;\n\t"
            "W%=:\n\t"
            "mbarrier.try_wait.parity.acquire.cluster.shared::cta.b64 P1, [%0], %1, 0x989680;\n\t"
            "@P1 bra.uni D%=;\n\t"
            "bra.uni W%=;\n\t"
            "D%=:\n\t}"
            :: "r"(mbar), "r"(parity) : "memory");
    }
}

__global__ __launch_bounds__(TPB2, 1) __cluster_dims__(4, 1, 1)
void gru_fused(const float* __restrict__ x,
               const float* __restrict__ Wih,
               const float* __restrict__ Whh,
               const float* __restrict__ bih,
               const float* __restrict__ bhh,
               float* __restrict__ out)
{
    extern __shared__ char smem[];
    const uint32_t smb = (uint32_t)__cvta_generic_to_shared(smem);
    float* ps  = (float*)(smem + OFF_PS);
    float* bsm = (float*)(smem + OFF_BSM);

    const int tid  = threadIdx.x;
    const int wid  = tid >> 5;
    const int lane = tid & 31;
    const int gq   = lane >> 2;
    const int tq   = lane & 3;
    uint32_t srank;
    asm("mov.u32 %0, %%cluster_ctarank;" : "=r"(srank));
    const int s = (int)srank;
    const int g = blockIdx.x >> 2;
    const int kperm = ((s + 1) << 6);

    const int row0 = wid * 16 + gq;
    const int row1 = row0 + 8;
    const int r0g = ((row0 >> 6) << 8) + (s << 6) + (row0 & 63);
    const int r1g = ((row1 >> 6) << 8) + (s << 6) + (row1 & 63);

    // ---- init W_hh: W1 frags -> regs, W2 frags -> SMEM (permuted cols) ----
    uint32_t w1f[16][4];
    {
        const float* W0 = Whh + (size_t)r0g * 256;
        const float* W1 = Whh + (size_t)r1g * 256;
#pragma unroll
        for (int kt = 0; kt < 16; ++kt) {
            int c0 = (kt * 16 + tq * 2 + kperm) & 255;
            float w00 = W0[c0],     w01 = W0[c0 + 1];
            float w10 = W1[c0],     w11 = W1[c0 + 1];
            float w02 = W0[c0 + 8], w03 = W0[c0 + 9];
            float w12 = W1[c0 + 8], w13 = W1[c0 + 9];
            w1f[kt][0] = pkbf(w00, w01);
            w1f[kt][1] = pkbf(w10, w11);
            w1f[kt][2] = pkbf(w02, w03);
            w1f[kt][3] = pkbf(w12, w13);
            uint4 w2;
            w2.x = pkbf(bfres(w00), bfres(w01));
            w2.y = pkbf(bfres(w10), bfres(w11));
            w2.z = pkbf(bfres(w02), bfres(w03));
            w2.w = pkbf(bfres(w12), bfres(w13));
            *(uint4*)(smem + OFF_W2HH + (((wid * 16 + kt) * 32) + lane) * 16) = w2;
        }
    }
    // ---- init W_ih: both split terms -> SMEM (no permutation, K=128) ----
    {
        const float* W0 = Wih + (size_t)r0g * 128;
        const float* W1 = Wih + (size_t)r1g * 128;
#pragma unroll
        for (int kt = 0; kt < 8; ++kt) {
            int c0 = kt * 16 + tq * 2;
            float w00 = W0[c0],     w01 = W0[c0 + 1];
            float w10 = W1[c0],     w11 = W1[c0 + 1];
            float w02 = W0[c0 + 8], w03 = W0[c0 + 9];
            float w12 = W1[c0 + 8], w13 = W1[c0 + 9];
            uint4 w1v, w2v;
            w1v.x = pkbf(w00, w01); w1v.y = pkbf(w10, w11);
            w1v.z = pkbf(w02, w03); w1v.w = pkbf(w12, w13);
            w2v.x = pkbf(bfres(w00), bfres(w01));
            w2v.y = pkbf(bfres(w10), bfres(w11));
            w2v.z = pkbf(bfres(w02), bfres(w03));
            w2v.w = pkbf(bfres(w12), bfres(w13));
            uint32_t o = (uint32_t)(((wid * 8 + kt) * 32 + lane) * 16);
            *(uint4*)(smem + OFF_W1IH + o) = w1v;
            *(uint4*)(smem + OFF_W2IH + o) = w2v;
        }
    }
    // ---- biases ----
    if (tid < 192) {
        int grow = ((tid >> 6) << 8) + (s << 6) + (tid & 63);
        bsm[tid] = (tid < 128) ? (bhh[grow] + bih[grow]) : bhh[grow];
    } else if (tid < 256) {
        int grow = 512 + (s << 6) + (tid - 192);
        bsm[tid] = bih[grow];
    }
    for (int i = tid; i < 16384 / 4; i += TPB2)
        ((float*)(smem + OFF_HSM))[i] = 0.f;
    if (tid == 0) {
        asm volatile("mbarrier.init.shared.b64 [%0], %1;"
                     :: "r"(smb + OFF_MBAR), "r"(4u) : "memory");
    }

    // ---- prologue: stage x(0) into xsm[0] ----
    const int sk  = tid & 127;
    const int sbp = tid >> 7;
    if (tid < 256) {
#pragma unroll
        for (int e = 0; e < 2; ++e) {
            int bp = sbp + 2 * e;
            float v0 = x[((size_t)(g * 8 + 2 * bp) * TT) * II + sk];
            float v1 = x[((size_t)(g * 8 + 2 * bp + 1) * TT) * II + sk];
            uint32_t hi = pkbf(v0, v1);
            uint32_t lo = pkbf(bfres(v0), bfres(v1));
            uint32_t a = smb + (uint32_t)(OFF_XSM + sk * 32 +
                                          (((sk >> 2) & 1) << 4) + bp * 4);
            asm volatile("st.shared.b32 [%0], %1;" :: "r"(a), "r"(hi) : "memory");
            asm volatile("st.shared.b32 [%0], %1;" :: "r"(a ^ 16u), "r"(lo) : "memory");
        }
    }
    __syncthreads();
    asm volatile("barrier.cluster.arrive.aligned;" ::: "memory");
    asm volatile("barrier.cluster.wait.aligned;" ::: "memory");

    const int jj = tid >> 2;
    const int bq = (tid & 3) * 2;
    const int kln = lane & 15;
    const uint32_t khx = (uint32_t)(lane >> 4) << 4;   // hi/lo select for x4t

    float br = 0.f, bz = 0.f, bhn = 0.f, bxn = 0.f;
    if (tid < 256) {
        br  = bsm[jj];       bz  = bsm[64 + jj];
        bhn = bsm[128 + jj]; bxn = bsm[192 + jj];
    }

    const uint32_t pushbase = (uint32_t)(OFF_HSM + jj * 32 + (((jj >> 2) & 1) << 4) + bq * 2);

    const char* w2p   = smem + OFF_W2HH + (size_t)wid * 8192 + lane * 16;
    const char* w1ihp = smem + OFF_W1IH + (size_t)wid * 4096 + lane * 16;
    const char* w2ihp = smem + OFF_W2IH + (size_t)wid * 4096 + lane * 16;

    float2 ho = make_float2(0.f, 0.f);

    for (int t = 0; t < TT; ++t) {
        const int p = t & 1;
        const uint32_t hbase = smb + (uint32_t)(OFF_HSM + p * 8192);
        const uint32_t xbase = smb + (uint32_t)(OFF_XSM + p * 4096);

        // prefetch x(t+1)
        float xp0 = 0.f, xp1 = 0.f, xp2 = 0.f, xp3 = 0.f;
        if (tid < 256 && t + 1 < TT) {
            xp0 = x[((size_t)(g * 8 + 2 * sbp) * TT + t + 1) * II + sk];
            xp1 = x[((size_t)(g * 8 + 2 * sbp + 1) * TT + t + 1) * II + sk];
            xp2 = x[((size_t)(g * 8 + 2 * (sbp + 2)) * TT + t + 1) * II + sk];
            xp3 = x[((size_t)(g * 8 + 2 * (sbp + 2) + 1) * TT + t + 1) * II + sk];
        }

        float e0 = 0.f, e1 = 0.f, e2 = 0.f, e3 = 0.f;   // hh even kt
        float o0 = 0.f, o1 = 0.f, o2 = 0.f, o3 = 0.f;   // hh odd kt
        float q0 = 0.f, q1 = 0.f, q2 = 0.f, q3 = 0.f;   // ih chain

        // ---- GEMM-ih: x(t) — fully local, no wait ----
#pragma unroll
        for (int kt = 0; kt < 8; ++kt) {
            int k0 = kt * 16 + kln;
            uint32_t addr = (xbase + (uint32_t)(k0 * 32 + (((k0 >> 2) & 1) << 4))) ^ khx;
            uint32_t bh0, bh1, bl0, bl1;
            ldsm_x4t(bh0, bh1, bl0, bl1, addr);
            uint4 w1 = *(const uint4*)(w1ihp + kt * 512);
            uint4 w2 = *(const uint4*)(w2ihp + kt * 512);
            mma16816(q0, q1, q2, q3, w1.x, w1.y, w1.z, w1.w, bh0, bh1);
            mma16816(q0, q1, q2, q3, w1.x, w1.y, w1.z, w1.w, bl0, bl1);
            mma16816(q0, q1, q2, q3, w2.x, w2.y, w2.z, w2.w, bh0, bh1);
        }

        // ---- GEMM-A: OWN hh slots (kt 12..15) — local, no wait ----
#pragma unroll
        for (int kt = 12; kt < 16; ++kt) {
            int k0 = kt * 16 + kln;
            uint32_t addr = (hbase + (uint32_t)(k0 * 32 + (((k0 >> 2) & 1) << 4))) ^ khx;
            uint32_t bh0, bh1, bl0, bl1;
            ldsm_x4t(bh0, bh1, bl0, bl1, addr);
            uint4 w2 = *(const uint4*)(w2p + kt * 512);
            if (kt & 1) {
                mma16816(o0, o1, o2, o3,
                         w1f[kt][0], w1f[kt][1], w1f[kt][2], w1f[kt][3], bh0, bh1);
                mma16816(o0, o1, o2, o3,
                         w1f[kt][0], w1f[kt][1], w1f[kt][2], w1f[kt][3], bl0, bl1);
                mma16816(o0, o1, o2, o3, w2.x, w2.y, w2.z, w2.w, bh0, bh1);
            } else {
                mma16816(e0, e1, e2, e3,
                         w1f[kt][0], w1f[kt][1], w1f[kt][2], w1f[kt][3], bh0, bh1);
                mma16816(e0, e1, e2, e3,
                         w1f[kt][0], w1f[kt][1], w1f[kt][2], w1f[kt][3], bl0, bl1);
                mma16816(e0, e1, e2, e3, w2.x, w2.y, w2.z, w2.w, bh0, bh1);
            }
        }

        // ---- wait for peers' step t-1 pushes ----
        if (t) mbar_waitc(smb + OFF_MBAR, (uint32_t)((t - 1) & 1));

        // ---- GEMM-B: peer hh slots (kt 0..11) ----
#pragma unroll
        for (int kt = 0; kt < 12; ++kt) {
            int k0 = kt * 16 + kln;
            uint32_t addr = (hbase + (uint32_t)(k0 * 32 + (((k0 >> 2) & 1) << 4))) ^ khx;
            uint32_t bh0, bh1, bl0, bl1;
            ldsm_x4t(bh0, bh1, bl0, bl1, addr);
            uint4 w2 = *(const uint4*)(w2p + kt * 512);
            if (kt & 1) {
                mma16816(o0, o1, o2, o3,
                         w1f[kt][0], w1f[kt][1], w1f[kt][2], w1f[kt][3], bh0, bh1);
                mma16816(o0, o1, o2, o3,
                         w1f[kt][0], w1f[kt][1], w1f[kt][2], w1f[kt][3], bl0, bl1);
                mma16816(o0, o1, o2, o3, w2.x, w2.y, w2.z, w2.w, bh0, bh1);
            } else {
                mma16816(e0, e1, e2, e3,
                         w1f[kt][0], w1f[kt][1], w1f[kt][2], w1f[kt][3], bh0, bh1);
                mma16816(e0, e1, e2, e3,
                         w1f[kt][0], w1f[kt][1], w1f[kt][2], w1f[kt][3], bl0, bl1);
                mma16816(e0, e1, e2, e3, w2.x, w2.y, w2.z, w2.w, bh0, bh1);
            }
        }

        // ---- deposit: r/z rows fuse ih; n rows keep ih separate ----
        {
            float v0 = e0 + o0, v1 = e1 + o1, v2 = e2 + o2, v3 = e3 + o3;
            if (wid < 8) { v0 += q0; v1 += q1; v2 += q2; v3 += q3; }
            *(float2*)(ps + row0 * 8 + tq * 2) = make_float2(v0, v1);
            *(float2*)(ps + row1 * 8 + tq * 2) = make_float2(v2, v3);
            if (wid >= 8) {
                *(float2*)(ps + (row0 + 64) * 8 + tq * 2) = make_float2(q0, q1);
                *(float2*)(ps + (row1 + 64) * 8 + tq * 2) = make_float2(q2, q3);
            }
        }
        __syncthreads();

        // ---- gates (8 warps) ----
        float hw0 = 0.f, hw1 = 0.f;
        if (tid < 256) {
            float2 rz = *(const float2*)(ps + jj * 8 + bq);
            float2 zz = *(const float2*)(ps + (64 + jj) * 8 + bq);
            float2 hn = *(const float2*)(ps + (128 + jj) * 8 + bq);
            float2 xn = *(const float2*)(ps + (192 + jj) * 8 + bq);

            float r0g_ = __fdividef(1.f, 1.f + __expf(-(rz.x + br)));
            float z0g_ = __fdividef(1.f, 1.f + __expf(-(zz.x + bz)));
            float v0   = xn.x + bxn + r0g_ * (hn.x + bhn);
            float n0   = 1.f - 2.f * __fdividef(1.f, __expf(2.f * v0) + 1.f);
            hw0 = (1.f - z0g_) * n0 + z0g_ * ho.x;

            float r1g_ = __fdividef(1.f, 1.f + __expf(-(rz.y + br)));
            float z1g_ = __fdividef(1.f, 1.f + __expf(-(zz.y + bz)));
            float v1   = xn.y + bxn + r1g_ * (hn.y + bhn);
            float n1   = 1.f - 2.f * __fdividef(1.f, __expf(2.f * v1) + 1.f);
            hw1 = (1.f - z1g_) * n1 + z1g_ * ho.y;

            uint32_t hiw = pkbf(hw0, hw1);
            uint32_t low = pkbf(bfres(hw0), bfres(hw1));

            uint32_t base = smb + pushbase + (uint32_t)((1 - p) * 8192);
            asm volatile("st.shared.b32 [%0], %1;"
                         :: "r"(base + 6144u), "r"(hiw) : "memory");
            asm volatile("st.shared.b32 [%0], %1;"
                         :: "r"((base + 6144u) ^ 16u), "r"(low) : "memory");
#pragma unroll
            for (int rk = 0; rk < 4; ++rk) {
                if (rk == s) continue;
                uint32_t cslot = (uint32_t)(((s - rk - 1) & 3) << 11);
                uint32_t ra, rb;
                asm volatile("mapa.shared::cluster.u32 %0, %1, %2;"
                             : "=r"(ra) : "r"(base + cslot), "r"(rk));
                asm volatile("mapa.shared::cluster.u32 %0, %1, %2;"
                             : "=r"(rb) : "r"((base + cslot) ^ 16u), "r"(rk));
                asm volatile("st.shared::cluster.b32 [%0], %1;"
                             :: "r"(ra), "r"(hiw) : "memory");
                asm volatile("st.shared::cluster.b32 [%0], %1;"
                             :: "r"(rb), "r"(low) : "memory");
            }
            ho = make_float2(hw0, hw1);

            // ---- stage x(t+1) into xsm[1-p] ----
            if (t + 1 < TT) {
                uint32_t xa = smb + (uint32_t)(OFF_XSM + (1 - p) * 4096 +
                              sk * 32 + (((sk >> 2) & 1) << 4));
                uint32_t h0 = pkbf(xp0, xp1);
                uint32_t l0 = pkbf(bfres(xp0), bfres(xp1));
                uint32_t h1 = pkbf(xp2, xp3);
                uint32_t l1 = pkbf(bfres(xp2), bfres(xp3));
                uint32_t a0 = xa + (uint32_t)(sbp * 4);
                uint32_t a1 = xa + (uint32_t)((sbp + 2) * 4);
                asm volatile("st.shared.b32 [%0], %1;" :: "r"(a0), "r"(h0) : "memory");
                asm volatile("st.shared.b32 [%0], %1;" :: "r"(a0 ^ 16u), "r"(l0) : "memory");
                asm volatile("st.shared.b32 [%0], %1;" :: "r"(a1), "r"(h1) : "memory");
                asm volatile("st.shared.b32 [%0], %1;" :: "r"(a1 ^ 16u), "r"(l1) : "memory");
            }

            // gate warps only: sync among 256 threads, then lane signals
            asm volatile("bar.sync 1, 256;" ::: "memory");
            if (tid == 0) {
                asm volatile("fence.acq_rel.cluster;" ::: "memory");
#pragma unroll
                for (int rk = 0; rk < 4; ++rk) {
                    uint32_t ra;
                    asm volatile("mapa.shared::cluster.u32 %0, %1, %2;"
                                 : "=r"(ra) : "r"(smb + OFF_MBAR), "r"(rk));
                    asm volatile("mbarrier.arrive.shared::cluster.b64 _, [%0];"
                                 :: "r"(ra) : "memory");
                }
            }
            size_t ob = ((size_t)(g * 8 + bq) * TT + t) * HH + (s << 6) + jj;
            out[ob] = hw0;
            out[ob + (size_t)TT * HH] = hw1;
        }
        __syncthreads();   // full-CTA: xsm[1-p], hsm own-slot, ps reuse safe
    }

    asm volatile("barrier.cluster.arrive.aligned;" ::: "memory");
    asm volatile("barrier.cluster.wait.aligned;" ::: "memory");
}

// ---------------------------------------------------------------------------
extern "C" void kernel_launch(void* const* d_in, const int* in_sizes, int n_in,
                              void* d_out, int out_size)
{
    const float* x   = (const float*)d_in[0];
    const float* Wih = (const float*)d_in[1];
    const float* Whh = (const float*)d_in[2];
    const float* bih = (const float*)d_in[3];
    const float* bhh = (const float*)d_in[4];
    float* out = (float*)d_out;

    cudaFuncSetAttribute(gru_fused,
                         cudaFuncAttributeMaxDynamicSharedMemorySize, SM2_BYTES);

    gru_fused<<<128, TPB2, SM2_BYTES>>>(x, Wih, Whh, bih, bhh, out);
}

// round 17
// speedup vs baseline: 1.2214x; 1.2214x over previous
#include <cuda_runtime.h>
#include <cuda_bf16.h>
#include <cstdint>
#include <cstddef>

#define BB 256
#define TT 512
#define II 128
#define HH 256
#define GG 768

typedef unsigned long long u64;

// ---------------- bf16 helpers ----------------
__device__ __forceinline__ uint32_t pkbf(float x, float y) {
    __nv_bfloat162 h = __floats2bfloat162_rn(x, y);
    return *(uint32_t*)&h;
}
__device__ __forceinline__ float bfres(float x) {   // x - bf16(x)
    return x - __bfloat162float(__float2bfloat16(x));
}
__device__ __forceinline__ void ldsm_x2t(uint32_t& r0, uint32_t& r1, uint32_t a) {
    asm volatile("ldmatrix.sync.aligned.m8n8.x2.trans.shared.b16 {%0,%1}, [%2];"
                 : "=r"(r0), "=r"(r1) : "r"(a));
}
__device__ __forceinline__ void mma16816(float& c0, float& c1, float& c2, float& c3,
                                         uint32_t a0, uint32_t a1, uint32_t a2, uint32_t a3,
                                         uint32_t b0, uint32_t b1) {
    asm("mma.sync.aligned.m16n8k16.row.col.f32.bf16.bf16.f32 "
        "{%0,%1,%2,%3}, {%4,%5,%6,%7}, {%8,%9}, {%0,%1,%2,%3};"
        : "+f"(c0), "+f"(c1), "+f"(c2), "+f"(c3)
        : "r"(a0), "r"(a1), "r"(a2), "r"(a3), "r"(b0), "r"(b1));
}

// ---------------------------------------------------------------------------
// FUSED GRU (R15 structure + x-staging offloaded to warps 8-11).
// 32 clusters x 4 CTAs, 384 threads. Per step, each warp's GEMM covers
// K = 128 (x, staged 1 step ahead by warps 8-11) + 256 (h, k-permuted
// own-slice overlap).
// ---------------------------------------------------------------------------
#define TPB2 384

#define OFF_W2HH 0                        // 12*16*32*16 = 98304
#define OFF_W1IH 98304                    // 12*8*32*16  = 49152
#define OFF_W2IH 147456                   // 49152
#define OFF_HSM  196608                   // 2*256*32 = 16384
#define OFF_XSM  212992                   // 2*128*32 = 8192
#define OFF_PS   221184                   // 256*8*4  = 8192
#define OFF_BSM  229376                   // 256*4 = 1024
#define OFF_MBAR 230400                   // 8
#define SM2_BYTES 230408

__device__ __forceinline__ void mbar_waitc(uint32_t mbar, uint32_t parity) {
    uint32_t done;
    asm volatile(
        "{\n\t.reg .pred p;\n\t"
        "mbarrier.try_wait.parity.acquire.cluster.shared::cta.b64 p, [%1], %2;\n\t"
        "selp.b32 %0, 1, 0, p;\n\t}"
        : "=r"(done) : "r"(mbar), "r"(parity) : "memory");
    if (!done) {
        asm volatile(
            "{\n\t.reg .pred P1;\n\t"
            "W%=:\n\t"
            "mbarrier.try_wait.parity.acquire.cluster.shared::cta.b64 P1, [%0], %1, 0x989680;\n\t"
            "@P1 bra.uni D%=;\n\t"
            "bra.uni W%=;\n\t"
            "D%=:\n\t}"
            :: "r"(mbar), "r"(parity) : "memory");
    }
}

__global__ __launch_bounds__(TPB2, 1) __cluster_dims__(4, 1, 1)
void gru_fused(const float* __restrict__ x,
               const float* __restrict__ Wih,
               const float* __restrict__ Whh,
               const float* __restrict__ bih,
               const float* __restrict__ bhh,
               float* __restrict__ out)
{
    extern __shared__ char smem[];
    const uint32_t smb = (uint32_t)__cvta_generic_to_shared(smem);
    float* ps  = (float*)(smem + OFF_PS);
    float* bsm = (float*)(smem + OFF_BSM);

    const int tid  = threadIdx.x;
    const int wid  = tid >> 5;
    const int lane = tid & 31;
    const int gq   = lane >> 2;
    const int tq   = lane & 3;
    uint32_t srank;
    asm("mov.u32 %0, %%cluster_ctarank;" : "=r"(srank));
    const int s = (int)srank;
    const int g = blockIdx.x >> 2;
    const int kperm = ((s + 1) << 6);

    const int row0 = wid * 16 + gq;
    const int row1 = row0 + 8;
    const int r0g = ((row0 >> 6) << 8) + (s << 6) + (row0 & 63);
    const int r1g = ((row1 >> 6) << 8) + (s << 6) + (row1 & 63);

    // ---- init W_hh: W1 frags -> regs, W2 frags -> SMEM (permuted cols) ----
    uint32_t w1f[16][4];
    {
        const float* W0 = Whh + (size_t)r0g * 256;
        const float* W1 = Whh + (size_t)r1g * 256;
#pragma unroll
        for (int kt = 0; kt < 16; ++kt) {
            int c0 = (kt * 16 + tq * 2 + kperm) & 255;
            float w00 = W0[c0],     w01 = W0[c0 + 1];
            float w10 = W1[c0],     w11 = W1[c0 + 1];
            float w02 = W0[c0 + 8], w03 = W0[c0 + 9];
            float w12 = W1[c0 + 8], w13 = W1[c0 + 9];
            w1f[kt][0] = pkbf(w00, w01);
            w1f[kt][1] = pkbf(w10, w11);
            w1f[kt][2] = pkbf(w02, w03);
            w1f[kt][3] = pkbf(w12, w13);
            uint4 w2;
            w2.x = pkbf(bfres(w00), bfres(w01));
            w2.y = pkbf(bfres(w10), bfres(w11));
            w2.z = pkbf(bfres(w02), bfres(w03));
            w2.w = pkbf(bfres(w12), bfres(w13));
            *(uint4*)(smem + OFF_W2HH + (((wid * 16 + kt) * 32) + lane) * 16) = w2;
        }
    }
    // ---- init W_ih: both split terms -> SMEM (no permutation, K=128) ----
    {
        const float* W0 = Wih + (size_t)r0g * 128;
        const float* W1 = Wih + (size_t)r1g * 128;
#pragma unroll
        for (int kt = 0; kt < 8; ++kt) {
            int c0 = kt * 16 + tq * 2;
            float w00 = W0[c0],     w01 = W0[c0 + 1];
            float w10 = W1[c0],     w11 = W1[c0 + 1];
            float w02 = W0[c0 + 8], w03 = W0[c0 + 9];
            float w12 = W1[c0 + 8], w13 = W1[c0 + 9];
            uint4 w1v, w2v;
            w1v.x = pkbf(w00, w01); w1v.y = pkbf(w10, w11);
            w1v.z = pkbf(w02, w03); w1v.w = pkbf(w12, w13);
            w2v.x = pkbf(bfres(w00), bfres(w01));
            w2v.y = pkbf(bfres(w10), bfres(w11));
            w2v.z = pkbf(bfres(w02), bfres(w03));
            w2v.w = pkbf(bfres(w12), bfres(w13));
            uint32_t o = (uint32_t)(((wid * 8 + kt) * 32 + lane) * 16);
            *(uint4*)(smem + OFF_W1IH + o) = w1v;
            *(uint4*)(smem + OFF_W2IH + o) = w2v;
        }
    }
    // ---- biases ----
    if (tid < 192) {
        int grow = ((tid >> 6) << 8) + (s << 6) + (tid & 63);
        bsm[tid] = (tid < 128) ? (bhh[grow] + bih[grow]) : bhh[grow];
    } else if (tid < 256) {
        int grow = 512 + (s << 6) + (tid - 192);
        bsm[tid] = bih[grow];
    }
    for (int i = tid; i < 16384 / 4; i += TPB2)
        ((float*)(smem + OFF_HSM))[i] = 0.f;
    if (tid == 0) {
        asm volatile("mbarrier.init.shared.b64 [%0], %1;"
                     :: "r"(smb + OFF_MBAR), "r"(4u) : "memory");
    }

    // ---- prologue: stage x(0) into xsm[0] (staging warps 8-11) ----
    const int sk = tid & 127;             // staging k column (tid>=256)
    if (tid >= 256) {
#pragma unroll
        for (int bp = 0; bp < 4; ++bp) {
            float v0 = x[((size_t)(g * 8 + 2 * bp) * TT) * II + sk];
            float v1 = x[((size_t)(g * 8 + 2 * bp + 1) * TT) * II + sk];
            uint32_t hi = pkbf(v0, v1);
            uint32_t lo = pkbf(bfres(v0), bfres(v1));
            uint32_t a = smb + (uint32_t)(OFF_XSM + sk * 32 +
                                          (((sk >> 2) & 1) << 4) + bp * 4);
            asm volatile("st.shared.b32 [%0], %1;" :: "r"(a), "r"(hi) : "memory");
            asm volatile("st.shared.b32 [%0], %1;" :: "r"(a ^ 16u), "r"(lo) : "memory");
        }
    }
    __syncthreads();
    asm volatile("barrier.cluster.arrive.aligned;" ::: "memory");
    asm volatile("barrier.cluster.wait.aligned;" ::: "memory");

    const int jj = tid >> 2;              // gate j (tid<256)
    const int bq = (tid & 3) * 2;         // gate batch pair
    const int kln = lane & 15;

    float br = 0.f, bz = 0.f, bhn = 0.f, bxn = 0.f;
    if (tid < 256) {
        br  = bsm[jj];       bz  = bsm[64 + jj];
        bhn = bsm[128 + jj]; bxn = bsm[192 + jj];
    }

    const uint32_t pushbase = (uint32_t)(OFF_HSM + jj * 32 + (((jj >> 2) & 1) << 4) + bq * 2);

    const char* w2p   = smem + OFF_W2HH + (size_t)wid * 8192 + lane * 16;
    const char* w1ihp = smem + OFF_W1IH + (size_t)wid * 4096 + lane * 16;
    const char* w2ihp = smem + OFF_W2IH + (size_t)wid * 4096 + lane * 16;

    float2 ho = make_float2(0.f, 0.f);

    for (int t = 0; t < TT; ++t) {
        const int p = t & 1;
        const uint32_t hbase = smb + (uint32_t)(OFF_HSM + p * 8192);
        const uint32_t xbase = smb + (uint32_t)(OFF_XSM + p * 4096);

        // prefetch x(t+1) — staging warps only (LDG hidden under GEMM)
        float xp[8];
        if (tid >= 256 && t + 1 < TT) {
#pragma unroll
            for (int bp = 0; bp < 4; ++bp) {
                xp[2 * bp]     = x[((size_t)(g * 8 + 2 * bp) * TT + t + 1) * II + sk];
                xp[2 * bp + 1] = x[((size_t)(g * 8 + 2 * bp + 1) * TT + t + 1) * II + sk];
            }
        }

        float e0 = 0.f, e1 = 0.f, e2 = 0.f, e3 = 0.f;   // hh even kt
        float o0 = 0.f, o1 = 0.f, o2 = 0.f, o3 = 0.f;   // hh odd kt
        float q0 = 0.f, q1 = 0.f, q2 = 0.f, q3 = 0.f;   // ih chain

        // ---- GEMM-ih: x(t) — fully local, no wait ----
#pragma unroll
        for (int kt = 0; kt < 8; ++kt) {
            int k0 = kt * 16 + kln;
            uint32_t rowHi = xbase + (uint32_t)(k0 * 32 + (((k0 >> 2) & 1) << 4));
            uint32_t rowLo = rowHi ^ 16u;
            uint32_t bh0, bh1, bl0, bl1;
            ldsm_x2t(bh0, bh1, rowHi);
            ldsm_x2t(bl0, bl1, rowLo);
            uint4 w1 = *(const uint4*)(w1ihp + kt * 512);
            uint4 w2 = *(const uint4*)(w2ihp + kt * 512);
            mma16816(q0, q1, q2, q3, w1.x, w1.y, w1.z, w1.w, bh0, bh1);
            mma16816(q0, q1, q2, q3, w1.x, w1.y, w1.z, w1.w, bl0, bl1);
            mma16816(q0, q1, q2, q3, w2.x, w2.y, w2.z, w2.w, bh0, bh1);
        }

        // ---- GEMM-A: OWN hh slots (kt 12..15) — local, no wait ----
#pragma unroll
        for (int kt = 12; kt < 16; ++kt) {
            int k0 = kt * 16 + kln;
            uint32_t rowHi = hbase + (uint32_t)(k0 * 32 + (((k0 >> 2) & 1) << 4));
            uint32_t rowLo = rowHi ^ 16u;
            uint32_t bh0, bh1, bl0, bl1;
            ldsm_x2t(bh0, bh1, rowHi);
            ldsm_x2t(bl0, bl1, rowLo);
            uint4 w2 = *(const uint4*)(w2p + kt * 512);
            if (kt & 1) {
                mma16816(o0, o1, o2, o3,
                         w1f[kt][0], w1f[kt][1], w1f[kt][2], w1f[kt][3], bh0, bh1);
                mma16816(o0, o1, o2, o3,
                         w1f[kt][0], w1f[kt][1], w1f[kt][2], w1f[kt][3], bl0, bl1);
                mma16816(o0, o1, o2, o3, w2.x, w2.y, w2.z, w2.w, bh0, bh1);
            } else {
                mma16816(e0, e1, e2, e3,
                         w1f[kt][0], w1f[kt][1], w1f[kt][2], w1f[kt][3], bh0, bh1);
                mma16816(e0, e1, e2, e3,
                         w1f[kt][0], w1f[kt][1], w1f[kt][2], w1f[kt][3], bl0, bl1);
                mma16816(e0, e1, e2, e3, w2.x, w2.y, w2.z, w2.w, bh0, bh1);
            }
        }

        // ---- wait for peers' step t-1 pushes ----
        if (t) mbar_waitc(smb + OFF_MBAR, (uint32_t)((t - 1) & 1));

        // ---- GEMM-B: peer hh slots (kt 0..11) ----
#pragma unroll
        for (int kt = 0; kt < 12; ++kt) {
            int k0 = kt * 16 + kln;
            uint32_t rowHi = hbase + (uint32_t)(k0 * 32 + (((k0 >> 2) & 1) << 4));
            uint32_t rowLo = rowHi ^ 16u;
            uint32_t bh0, bh1, bl0, bl1;
            ldsm_x2t(bh0, bh1, rowHi);
            ldsm_x2t(bl0, bl1, rowLo);
            uint4 w2 = *(const uint4*)(w2p + kt * 512);
            if (kt & 1) {
                mma16816(o0, o1, o2, o3,
                         w1f[kt][0], w1f[kt][1], w1f[kt][2], w1f[kt][3], bh0, bh1);
                mma16816(o0, o1, o2, o3,
                         w1f[kt][0], w1f[kt][1], w1f[kt][2], w1f[kt][3], bl0, bl1);
                mma16816(o0, o1, o2, o3, w2.x, w2.y, w2.z, w2.w, bh0, bh1);
            } else {
                mma16816(e0, e1, e2, e3,
                         w1f[kt][0], w1f[kt][1], w1f[kt][2], w1f[kt][3], bh0, bh1);
                mma16816(e0, e1, e2, e3,
                         w1f[kt][0], w1f[kt][1], w1f[kt][2], w1f[kt][3], bl0, bl1);
                mma16816(e0, e1, e2, e3, w2.x, w2.y, w2.z, w2.w, bh0, bh1);
            }
        }

        // ---- deposit: r/z rows fuse ih; n rows keep ih separate ----
        {
            float v0 = e0 + o0, v1 = e1 + o1, v2 = e2 + o2, v3 = e3 + o3;
            if (wid < 8) { v0 += q0; v1 += q1; v2 += q2; v3 += q3; }
            *(float2*)(ps + row0 * 8 + tq * 2) = make_float2(v0, v1);
            *(float2*)(ps + row1 * 8 + tq * 2) = make_float2(v2, v3);
            if (wid >= 8) {
                *(float2*)(ps + (row0 + 64) * 8 + tq * 2) = make_float2(q0, q1);
                *(float2*)(ps + (row1 + 64) * 8 + tq * 2) = make_float2(q2, q3);
            }
        }
        __syncthreads();

        // ---- gates (warps 0-7) | x(t+1) staging (warps 8-11) ----
        float hw0 = 0.f, hw1 = 0.f;
        if (tid < 256) {
            float2 rz = *(const float2*)(ps + jj * 8 + bq);
            float2 zz = *(const float2*)(ps + (64 + jj) * 8 + bq);
            float2 hn = *(const float2*)(ps + (128 + jj) * 8 + bq);
            float2 xn = *(const float2*)(ps + (192 + jj) * 8 + bq);

            float r0g_ = __fdividef(1.f, 1.f + __expf(-(rz.x + br)));
            float z0g_ = __fdividef(1.f, 1.f + __expf(-(zz.x + bz)));
            float v0   = xn.x + bxn + r0g_ * (hn.x + bhn);
            float n0   = 1.f - 2.f * __fdividef(1.f, __expf(2.f * v0) + 1.f);
            hw0 = (1.f - z0g_) * n0 + z0g_ * ho.x;

            float r1g_ = __fdividef(1.f, 1.f + __expf(-(rz.y + br)));
            float z1g_ = __fdividef(1.f, 1.f + __expf(-(zz.y + bz)));
            float v1   = xn.y + bxn + r1g_ * (hn.y + bhn);
            float n1   = 1.f - 2.f * __fdividef(1.f, __expf(2.f * v1) + 1.f);
            hw1 = (1.f - z1g_) * n1 + z1g_ * ho.y;

            uint32_t hiw = pkbf(hw0, hw1);
            uint32_t low = pkbf(bfres(hw0), bfres(hw1));

            uint32_t base = smb + pushbase + (uint32_t)((1 - p) * 8192);
            asm volatile("st.shared.b32 [%0], %1;"
                         :: "r"(base + 6144u), "r"(hiw) : "memory");
            asm volatile("st.shared.b32 [%0], %1;"
                         :: "r"((base + 6144u) ^ 16u), "r"(low) : "memory");
#pragma unroll
            for (int rk = 0; rk < 4; ++rk) {
                if (rk == s) continue;
                uint32_t cslot = (uint32_t)(((s - rk - 1) & 3) << 11);
                uint32_t ra, rb;
                asm volatile("mapa.shared::cluster.u32 %0, %1, %2;"
                             : "=r"(ra) : "r"(base + cslot), "r"(rk));
                asm volatile("mapa.shared::cluster.u32 %0, %1, %2;"
                             : "=r"(rb) : "r"((base + cslot) ^ 16u), "r"(rk));
                asm volatile("st.shared::cluster.b32 [%0], %1;"
                             :: "r"(ra), "r"(hiw) : "memory");
                asm volatile("st.shared::cluster.b32 [%0], %1;"
                             :: "r"(rb), "r"(low) : "memory");
            }
            ho = make_float2(hw0, hw1);
        } else if (t + 1 < TT) {
            // ---- stage x(t+1) into xsm[1-p] (warps 8-11) ----
            uint32_t xa = smb + (uint32_t)(OFF_XSM + (1 - p) * 4096 +
                          sk * 32 + (((sk >> 2) & 1) << 4));
#pragma unroll
            for (int bp = 0; bp < 4; ++bp) {
                uint32_t hi = pkbf(xp[2 * bp], xp[2 * bp + 1]);
                uint32_t lo = pkbf(bfres(xp[2 * bp]), bfres(xp[2 * bp + 1]));
                uint32_t a = xa + (uint32_t)(bp * 4);
                asm volatile("st.shared.b32 [%0], %1;" :: "r"(a), "r"(hi) : "memory");
                asm volatile("st.shared.b32 [%0], %1;" :: "r"(a ^ 16u), "r"(lo) : "memory");
            }
        }
        __syncthreads();

        // ---- signal all ranks, THEN write outputs ----
        if (tid == 0) {
            asm volatile("fence.acq_rel.cluster;" ::: "memory");
#pragma unroll
            for (int rk = 0; rk < 4; ++rk) {
                uint32_t ra;
                asm volatile("mapa.shared::cluster.u32 %0, %1, %2;"
                             : "=r"(ra) : "r"(smb + OFF_MBAR), "r"(rk));
                asm volatile("mbarrier.arrive.shared::cluster.b64 _, [%0];"
                             :: "r"(ra) : "memory");
            }
        }
        if (tid < 256) {
            size_t ob = ((size_t)(g * 8 + bq) * TT + t) * HH + (s << 6) + jj;
            out[ob] = hw0;
            out[ob + (size_t)TT * HH] = hw1;
        }
    }

    asm volatile("barrier.cluster.arrive.aligned;" ::: "memory");
    asm volatile("barrier.cluster.wait.aligned;" ::: "memory");
}

// ---------------------------------------------------------------------------
extern "C" void kernel_launch(void* const* d_in, const int* in_sizes, int n_in,
                              void* d_out, int out_size)
{
    const float* x   = (const float*)d_in[0];
    const float* Wih = (const float*)d_in[1];
    const float* Whh = (const float*)d_in[2];
    const float* bih = (const float*)d_in[3];
    const float* bhh = (const float*)d_in[4];
    float* out = (float*)d_out;

    cudaFuncSetAttribute(gru_fused,
                         cudaFuncAttributeMaxDynamicSharedMemorySize, SM2_BYTES);

    gru_fused<<<128, TPB2, SM2_BYTES>>>(x, Wih, Whh, bih, bhh, out);
}